// round 5
// baseline (speedup 1.0000x reference)
#include <cuda_runtime.h>
#include <cstdint>

// B=4, M_IN=16, M_OUT=32, C=32.  x:(4,16,32,32,32,32) fp32 -> out:(4,32,4,32) fp32
//
//   s1[b,m,c2] = sum_{c3,c4,c5} x          (s2 == s1)
//   s3[b,m,c3] = sum_{c2,c4,c5} x
//   s4[b,m,c4] = sum_{c2,c3,c5} x
//   W = alpha+beta+gamma+delta (16x32)
//   out[b,n,i,c] = sum_m S_i[b,m,c] * W[m,n],  S = [s1,s1,s3,s4]
//
// SINGLE fused kernel, 4096 blocks (one half-slice each, R3-proven hot path).
// Completion chain (ticket atomics on int counters; FP math in fixed order ->
// bitwise deterministic):
//   level 0: 4096 blocks write partials, tick cnt_bm[bm] (64 per bm)
//   level 1: ticket-63 block folds bm -> g_S[bm][i][c], ticks cnt_b[b]
//   level 2: ticket-15 block computes b's 4096 outputs
//   level 3: ticket-3 final resets all counters for the next graph replay

__device__ float g_s1h[4096];            // [bid], bid = slice*2+half, slice=(b*16+m)*32+c2
__device__ float g_s3 [2048 * 32];       // [slice][c3]  (full over c4,c5; unique owner half)
__device__ float g_s4h[4096 * 32];       // [bid][c4]    (partial over this half's c3)
__device__ float g_S  [8192];            // [bm][i][c]
__device__ int   cnt_bm[64];
__device__ int   cnt_b[4];
__device__ int   cnt_fin;

__device__ __forceinline__ unsigned long long addx2(unsigned long long a,
                                                    unsigned long long b) {
    unsigned long long r;
    asm("add.rn.f32x2 %0, %1, %2;" : "=l"(r) : "l"(a), "l"(b));
    return r;
}
__device__ __forceinline__ float x2sum(unsigned long long a) {
    unsigned lo, hi;
    asm("mov.b64 {%0,%1}, %2;" : "=r"(lo), "=r"(hi) : "l"(a));
    return __uint_as_float(lo) + __uint_as_float(hi);
}
// evict-first 16B streaming load (read-once data; keep L2 for partials)
__device__ __forceinline__ ulonglong2 ldcs2(const ulonglong2* p) {
    ulonglong2 r;
    asm("ld.global.cs.v2.u64 {%0, %1}, [%2];" : "=l"(r.x), "=l"(r.y) : "l"(p));
    return r;
}

__global__ void __launch_bounds__(256, 4)
k_fused(const float* __restrict__ x,
        const float* __restrict__ wa, const float* __restrict__ wb,
        const float* __restrict__ wg, const float* __restrict__ wd,
        float* __restrict__ out) {
    const int t    = threadIdx.x;
    const int lane = t & 31;
    const int w    = t >> 5;
    const int bid  = blockIdx.x;          // half-slice id
    const int slice = bid >> 1;
    const int half  = bid & 1;

    const ulonglong2* __restrict__ xv =
        reinterpret_cast<const ulonglong2*>(x) + (size_t)bid * 4096; // 16384 floats

    __shared__ float pp[256];             // s4buf in main; scratch in fold
    __shared__ float wt[8];
    __shared__ float sW[512];             // used only by final blocks
    __shared__ int   s_tick;

    // ================= main: half-slice reduction (R3 hot path) =================
    unsigned long long col[8];
#pragma unroll
    for (int s = 0; s < 8; ++s) col[s] = 0ull;

    float rows_tot = 0.f;                 // valid on lane 0
#pragma unroll
    for (int j = 0; j < 2; ++j) {
        const int k = w + j * 8;          // local row 0..15  (c3 = half*16 + k)
        const ulonglong2* __restrict__ p = xv + k * 256 + lane;

        ulonglong2 d[8];
#pragma unroll
        for (int s = 0; s < 8; ++s) d[s] = ldcs2(p + s * 32);   // 8 back-to-back LDG.128

        unsigned long long row = 0ull;
#pragma unroll
        for (int s = 0; s < 8; ++s) {
            unsigned long long v = addx2(d[s].x, d[s].y);  // {f0+f2, f1+f3}
            row    = addx2(row, v);
            col[s] = addx2(col[s], v);
        }
        float r = x2sum(row);
#pragma unroll
        for (int o = 16; o; o >>= 1) r += __shfl_down_sync(0xffffffffu, r, o);
        if (lane == 0) {
            g_s3[slice * 32 + half * 16 + k] = r;   // full s3 entry (unique owner)
            rows_tot += r;
        }
    }

#pragma unroll
    for (int s = 0; s < 8; ++s) {
        float cs = x2sum(col[s]);
        cs += __shfl_down_sync(0xffffffffu, cs, 4);
        cs += __shfl_down_sync(0xffffffffu, cs, 2);
        cs += __shfl_down_sync(0xffffffffu, cs, 1);
        if ((lane & 7) == 0) pp[w * 32 + s * 4 + (lane >> 3)] = cs;
    }
    if (lane == 0) wt[w] = rows_tot;
    __syncthreads();

    if (t < 32) {        // warp 0: cross-warp s4 fold + slice total
        float v = 0.f;
#pragma unroll
        for (int ww = 0; ww < 8; ++ww) v += pp[ww * 32 + t];
        g_s4h[bid * 32 + t] = v;
        if (t == 0) {
            float s = 0.f;
#pragma unroll
            for (int ww = 0; ww < 8; ++ww) s += wt[ww];
            g_s1h[bid] = s;
        }
    }

    // ================= level 0 -> 1: tick bm counter =================
    const int bm = bid >> 6;
    __syncthreads();
    if (t == 0) { __threadfence(); s_tick = atomicAdd(&cnt_bm[bm], 1); }
    __syncthreads();
    if (s_tick != 63) return;

    // ================= level 1: fold this bm -> g_S[bm][i][c] =================
    __threadfence();
    {
        float v = 0.f;
        if (t < 32) {
            v = g_s1h[(bm * 32 + t) * 2] + g_s1h[(bm * 32 + t) * 2 + 1];
        } else if (t >= 64 && t < 128) {
            const int c3 = (t - 64) & 31, part = (t - 64) >> 5;
            const float* __restrict__ p = g_s3 + bm * 1024 + part * 512 + c3;
#pragma unroll
            for (int q = 0; q < 16; ++q) v += p[q * 32];      // over c2
        } else if (t >= 128) {
            const int c4 = (t - 128) & 31, part = (t - 128) >> 5;   // part 0..3
            const float* __restrict__ p = g_s4h + (bm * 64 + part * 16) * 32 + c4;
#pragma unroll
            for (int q = 0; q < 16; ++q) v += p[q * 32];      // over (c2,half)
        }
        pp[t] = v;
    }
    __syncthreads();
    if (t < 32) {
        const float s1v = pp[t];
        const float s3v = pp[64 + t] + pp[96 + t];
        const float s4v = pp[128 + t] + pp[160 + t] + pp[192 + t] + pp[224 + t];
        g_S[bm * 128 +       t] = s1v;
        g_S[bm * 128 +  32 + t] = s1v;
        g_S[bm * 128 +  64 + t] = s3v;
        g_S[bm * 128 +  96 + t] = s4v;
    }

    // ================= level 1 -> 2: tick b counter =================
    __syncthreads();
    if (t == 0) { __threadfence(); s_tick = atomicAdd(&cnt_b[bm >> 4], 1); }
    __syncthreads();
    if (s_tick != 15) return;

    // ================= level 2: einsum for this b =================
    const int b = bm >> 4;
    __threadfence();
    sW[t]       = wa[t]       + wb[t]       + wg[t]       + wd[t];
    sW[t + 256] = wa[t + 256] + wb[t + 256] + wg[t + 256] + wd[t + 256];
    __syncthreads();

    {
        const int combo = t >> 1;         // 0..127 : (i,c)
        const int nh    = t & 1;          // n half
        const int i = combo >> 5;
        const int c = combo & 31;
        float S[16];
#pragma unroll
        for (int m = 0; m < 16; ++m) S[m] = g_S[(b * 16 + m) * 128 + i * 32 + c];
#pragma unroll
        for (int n0 = 0; n0 < 16; ++n0) {
            const int n = nh * 16 + n0;
            float acc = 0.f;
#pragma unroll
            for (int m = 0; m < 16; ++m) acc += S[m] * sW[m * 32 + n];
            out[((b * 32 + n) * 4 + i) * 32 + c] = acc;
        }
    }

    // ================= level 3: last final resets counters =================
    if (t == 0) {
        __threadfence();
        if (atomicAdd(&cnt_fin, 1) == 3) {
#pragma unroll
            for (int q = 0; q < 64; ++q) cnt_bm[q] = 0;
            cnt_b[0] = cnt_b[1] = cnt_b[2] = cnt_b[3] = 0;
            cnt_fin = 0;
        }
    }
}

// ---------------- launch ----------------
extern "C" void kernel_launch(void* const* d_in, const int* in_sizes, int n_in,
                              void* d_out, int out_size) {
    const float* x     = (const float*)d_in[0];
    const float* alpha = (const float*)d_in[1];
    const float* beta  = (const float*)d_in[2];
    const float* gamma = (const float*)d_in[3];
    const float* delta = (const float*)d_in[4];

    k_fused<<<4096, 256>>>(x, alpha, beta, gamma, delta, (float*)d_out);
}

// round 6
// speedup vs baseline: 1.0367x; 1.0367x over previous
#include <cuda_runtime.h>
#include <cstdint>

// B=4, M_IN=16, M_OUT=32, C=32.  x:(4,16,32,32,32,32) fp32 -> out:(4,32,4,32) fp32
//
//   s1[b,m,c2] = sum_{c3,c4,c5} x          (s2 == s1)
//   s3[b,m,c3] = sum_{c2,c4,c5} x
//   s4[b,m,c4] = sum_{c2,c3,c5} x
//   W = alpha+beta+gamma+delta (16x32)
//   out[b,n,i,c] = sum_m S_i[b,m,c] * W[m,n],  S = [s1,s1,s3,s4]
//
// SINGLE fused kernel, 4096 blocks (one half-slice each, R3-proven hot path).
// Completion chain uses acq_rel ticket atomics (NO __threadfence -> no
// CCTL.IVALL L1 flush, which caused the R5 regression). Consumers read
// cross-SM partials with __ldcg (L2-only). FP order fixed -> deterministic.
//   level 0: 4096 blocks write partials, tick cnt_bm[bm] (64 per bm)
//   level 1: ticket-63 block folds bm -> g_S[bm][i][c], ticks cnt_b[b]
//   level 2: ticket-15 block computes b's 4096 outputs
//   level 3: ticket-3 final resets all counters for the next graph replay

__device__ float g_s1h[4096];            // [bid], bid = slice*2+half, slice=(b*16+m)*32+c2
__device__ float g_s3 [2048 * 32];       // [slice][c3]  (full over c4,c5; unique owner half)
__device__ float g_s4h[4096 * 32];       // [bid][c4]    (partial over this half's c3)
__device__ float g_S  [8192];            // [bm][i][c]
__device__ int   cnt_bm[64];
__device__ int   cnt_b[4];
__device__ int   cnt_fin;

__device__ __forceinline__ unsigned long long addx2(unsigned long long a,
                                                    unsigned long long b) {
    unsigned long long r;
    asm("add.rn.f32x2 %0, %1, %2;" : "=l"(r) : "l"(a), "l"(b));
    return r;
}
__device__ __forceinline__ float x2sum(unsigned long long a) {
    unsigned lo, hi;
    asm("mov.b64 {%0,%1}, %2;" : "=r"(lo), "=r"(hi) : "l"(a));
    return __uint_as_float(lo) + __uint_as_float(hi);
}
// evict-first 16B streaming load (read-once data; keep L2 for partials)
__device__ __forceinline__ ulonglong2 ldcs2(const ulonglong2* p) {
    ulonglong2 r;
    asm("ld.global.cs.v2.u64 {%0, %1}, [%2];" : "=l"(r.x), "=l"(r.y) : "l"(p));
    return r;
}
// gpu-scope acq_rel ticket (no membar/CCTL.IVALL)
__device__ __forceinline__ int ticket(int* p) {
    int old;
    asm volatile("atom.acq_rel.gpu.global.add.s32 %0, [%1], 1;"
                 : "=r"(old) : "l"(p) : "memory");
    return old;
}

__global__ void __launch_bounds__(256, 4)
k_fused(const float* __restrict__ x,
        const float* __restrict__ wa, const float* __restrict__ wb,
        const float* __restrict__ wg, const float* __restrict__ wd,
        float* __restrict__ out) {
    const int t    = threadIdx.x;
    const int lane = t & 31;
    const int w    = t >> 5;
    const int bid  = blockIdx.x;          // half-slice id
    const int slice = bid >> 1;
    const int half  = bid & 1;

    const ulonglong2* __restrict__ xv =
        reinterpret_cast<const ulonglong2*>(x) + (size_t)bid * 4096; // 16384 floats

    __shared__ float pp[256];             // s4buf in main; scratch in fold
    __shared__ float wt[8];
    __shared__ float sW[512];             // used only by final blocks
    __shared__ int   s_tick;

    // ================= main: half-slice reduction (R3 hot path) =================
    unsigned long long col[8];
#pragma unroll
    for (int s = 0; s < 8; ++s) col[s] = 0ull;

    float rows_tot = 0.f;                 // valid on lane 0
#pragma unroll
    for (int j = 0; j < 2; ++j) {
        const int k = w + j * 8;          // local row 0..15  (c3 = half*16 + k)
        const ulonglong2* __restrict__ p = xv + k * 256 + lane;

        ulonglong2 d[8];
#pragma unroll
        for (int s = 0; s < 8; ++s) d[s] = ldcs2(p + s * 32);   // 8 back-to-back LDG.128

        unsigned long long row = 0ull;
#pragma unroll
        for (int s = 0; s < 8; ++s) {
            unsigned long long v = addx2(d[s].x, d[s].y);  // {f0+f2, f1+f3}
            row    = addx2(row, v);
            col[s] = addx2(col[s], v);
        }
        float r = x2sum(row);
#pragma unroll
        for (int o = 16; o; o >>= 1) r += __shfl_down_sync(0xffffffffu, r, o);
        if (lane == 0) {
            g_s3[slice * 32 + half * 16 + k] = r;   // full s3 entry (unique owner)
            rows_tot += r;
        }
    }

#pragma unroll
    for (int s = 0; s < 8; ++s) {
        float cs = x2sum(col[s]);
        cs += __shfl_down_sync(0xffffffffu, cs, 4);
        cs += __shfl_down_sync(0xffffffffu, cs, 2);
        cs += __shfl_down_sync(0xffffffffu, cs, 1);
        if ((lane & 7) == 0) pp[w * 32 + s * 4 + (lane >> 3)] = cs;
    }
    if (lane == 0) wt[w] = rows_tot;
    __syncthreads();

    if (t < 32) {        // warp 0: cross-warp s4 fold + slice total
        float v = 0.f;
#pragma unroll
        for (int ww = 0; ww < 8; ++ww) v += pp[ww * 32 + t];
        g_s4h[bid * 32 + t] = v;
        if (t == 0) {
            float s = 0.f;
#pragma unroll
            for (int ww = 0; ww < 8; ++ww) s += wt[ww];
            g_s1h[bid] = s;
        }
    }

    // ================= level 0 -> 1: tick bm counter (acq_rel, no fence) ==========
    const int bm = bid >> 6;
    __syncthreads();
    if (t == 0) s_tick = ticket(&cnt_bm[bm]);
    __syncthreads();
    if (s_tick != 63) return;

    // ================= level 1: fold this bm -> g_S[bm][i][c] =================
    {
        float v = 0.f;
        if (t < 32) {
            v = __ldcg(&g_s1h[(bm * 32 + t) * 2]) + __ldcg(&g_s1h[(bm * 32 + t) * 2 + 1]);
        } else if (t >= 64 && t < 128) {
            const int c3 = (t - 64) & 31, part = (t - 64) >> 5;
            const float* __restrict__ p = g_s3 + bm * 1024 + part * 512 + c3;
#pragma unroll
            for (int q = 0; q < 16; ++q) v += __ldcg(p + q * 32);   // over c2
        } else if (t >= 128) {
            const int c4 = (t - 128) & 31, part = (t - 128) >> 5;   // part 0..3
            const float* __restrict__ p = g_s4h + (bm * 64 + part * 16) * 32 + c4;
#pragma unroll
            for (int q = 0; q < 16; ++q) v += __ldcg(p + q * 32);   // over (c2,half)
        }
        pp[t] = v;
    }
    __syncthreads();
    if (t < 32) {
        const float s1v = pp[t];
        const float s3v = pp[64 + t] + pp[96 + t];
        const float s4v = pp[128 + t] + pp[160 + t] + pp[192 + t] + pp[224 + t];
        g_S[bm * 128 +       t] = s1v;
        g_S[bm * 128 +  32 + t] = s1v;
        g_S[bm * 128 +  64 + t] = s3v;
        g_S[bm * 128 +  96 + t] = s4v;
    }

    // ================= level 1 -> 2: tick b counter =================
    __syncthreads();
    if (t == 0) s_tick = ticket(&cnt_b[bm >> 4]);
    __syncthreads();
    if (s_tick != 15) return;

    // ================= level 2: einsum for this b =================
    const int b = bm >> 4;
    sW[t]       = wa[t]       + wb[t]       + wg[t]       + wd[t];
    sW[t + 256] = wa[t + 256] + wb[t + 256] + wg[t + 256] + wd[t + 256];
    __syncthreads();

    {
        const int combo = t >> 1;         // 0..127 : (i,c)
        const int nh    = t & 1;          // n half
        const int i = combo >> 5;
        const int c = combo & 31;
        float S[16];
#pragma unroll
        for (int m = 0; m < 16; ++m) S[m] = __ldcg(&g_S[(b * 16 + m) * 128 + i * 32 + c]);
#pragma unroll
        for (int n0 = 0; n0 < 16; ++n0) {
            const int n = nh * 16 + n0;
            float acc = 0.f;
#pragma unroll
            for (int m = 0; m < 16; ++m) acc += S[m] * sW[m * 32 + n];
            out[((b * 32 + n) * 4 + i) * 32 + c] = acc;
        }
    }

    // ================= level 3: last final resets counters =================
    __syncthreads();
    if (t == 0 && ticket(&cnt_fin) == 3) {
#pragma unroll
        for (int q = 0; q < 64; ++q) cnt_bm[q] = 0;
        cnt_b[0] = cnt_b[1] = cnt_b[2] = cnt_b[3] = 0;
        cnt_fin = 0;
    }
}

// ---------------- launch ----------------
extern "C" void kernel_launch(void* const* d_in, const int* in_sizes, int n_in,
                              void* d_out, int out_size) {
    const float* x     = (const float*)d_in[0];
    const float* alpha = (const float*)d_in[1];
    const float* beta  = (const float*)d_in[2];
    const float* gamma = (const float*)d_in[3];
    const float* delta = (const float*)d_in[4];

    k_fused<<<4096, 256>>>(x, alpha, beta, gamma, delta, (float*)d_out);
}